// round 15
// baseline (speedup 1.0000x reference)
#include <cuda_runtime.h>
#include <cstdint>

#define S_LEN  2048
#define TB     16
#define NHEAD  4
#define NPOS   12
#define VBITS  10
#define OBITS  12
#define WARPS_PER_BLK 16   // one warp per position, 512 threads/block, 128 blocks

// Inputs (metadata order):
//  0: tokens       (S, 16)        int32  (0/1 bits)
//  1: route_table  (H, 1<<24)     int32  (0/1)
//  2: value_table  (H, 16, 1024)  float32
//  3: output_table (16, 4096)     float32
//  4: conns_value  (H, 16, 10)    int32  in [0, 28)
//  5: conns_out    (16, 12)       int32  in [0, 64)
// Output: (S, 16) float32
//
// FINAL (locked; bench 6.624us on 4 independent runs, regs 30, rel_err 0.0).
// The bench measurement is floor-bound: fixed graph-replay/launch overhead +
// single-wave warp ramp + an irreducible 3-level dependent L2 chain
// (route probe -> value lookup -> output lookup). All pipes <9%, DRAM ~2.3%.
//
// Design principles established over 14 rounds of measurement:
//  - one warp per position, maximum independent warps (serializing work per
//    warp or scattering per-lane conn loads regresses: R4, R7)
//  - ALL long-latency loads issued up front, before any dependency/barrier
//  - token rows 0..15 prefetched -> token stage moved off the memory chain
//  - 16-j route probe -> fallback probability 2^-16 per head (no block tail)
//  - __syncthreads placed before the ballots so it only orders the conns
//    preload; no warp ever waits on another warp's route latency
//  - rejected by model/measurement: speculative value prefetch (no chain
//    reduction), int4 route probe + shfl-reduce (longer ALU chain than one
//    ballot), bank-conflict padding, OR-tree address packs, fewer warps with
//    more work per warp (all flat or regressions)

__global__ __launch_bounds__(WARPS_PER_BLK * 32)
void poa_kernel(const int*   __restrict__ tokens,
                const int*   __restrict__ route_table,
                const float* __restrict__ value_table,
                const float* __restrict__ output_table,
                const int*   __restrict__ conns_value,
                const int*   __restrict__ conns_out,
                float*       __restrict__ out)
{
    // Conn tables staged in shared (coalesced int4 preload). cv=640, co=192 ints.
    __shared__ __align__(16) int s_cv[NHEAD * TB * VBITS];
    __shared__ __align__(16) int s_co[TB * OBITS];

    const int tid  = threadIdx.x;
    const int lane = tid & 31;
    const int wid  = tid >> 5;
    const int i    = blockIdx.x * WARPS_PER_BLK + wid;   // position

    // ---- independent front-loaded work: ALL loads issued before the barrier ----

    // (a) coalesced conns preload: 160 + 48 int4 over 512 threads.
    if (tid < NHEAD * TB * VBITS / 4)
        ((int4*)s_cv)[tid] = ((const int4*)conns_value)[tid];
    else if (tid < NHEAD * TB * VBITS / 4 + TB * OBITS / 4) {
        int k = tid - NHEAD * TB * VBITS / 4;
        ((int4*)s_co)[k] = ((const int4*)conns_out)[k];
    }

    // (b) candidate token rows 0..15: 16 rows x 16 ints = 64 int4, two per lane.
    //     For each int4: lane = (row&7)*4 + c ; nibble covers token bits 4c..4c+3.
    int4 ta4 = __ldg(&((const int4*)tokens)[lane]);        // rows 0..7
    int4 tb4 = __ldg(&((const int4*)tokens)[32 + lane]);   // rows 8..15

    // (c) route probes: lanes (h = lane>>3, j' = lane&7); two loads cover j<16/head
    const int h0   = lane >> 3;
    const int jl   = lane & 7;
    const int rbas = (h0 << 24) | (i << NPOS);
    int rv0 = __ldg(&route_table[rbas + jl]);        // j = 0..7
    int rv1 = __ldg(&route_table[rbas + 8 + jl]);    // j = 8..15

    // Barrier now: only orders the conns preload; all long-latency loads above
    // are already in flight, and nothing after this couples warps.
    __syncthreads();

    // pack token row masks while route loads complete
    unsigned ra, rb;
    {
        unsigned na = (unsigned)(ta4.x > 0) | ((unsigned)(ta4.y > 0) << 1)
                    | ((unsigned)(ta4.z > 0) << 2) | ((unsigned)(ta4.w > 0) << 3);
        unsigned nb = (unsigned)(tb4.x > 0) | ((unsigned)(tb4.y > 0) << 1)
                    | ((unsigned)(tb4.z > 0) << 2) | ((unsigned)(tb4.w > 0) << 3);
        ra = na << (4 * (lane & 3));
        rb = nb << (4 * (lane & 3));
        ra |= __shfl_xor_sync(0xffffffffu, ra, 1);
        ra |= __shfl_xor_sync(0xffffffffu, ra, 2);
        rb |= __shfl_xor_sync(0xffffffffu, rb, 1);
        rb |= __shfl_xor_sync(0xffffffffu, rb, 2);
        // group-of-4 lanes hold: ra = mask of row (lane>>2), rb = row 8+(lane>>2)
    }

    // ---- 1) j_first per head from 16 probed j's ----
    unsigned m0 = __ballot_sync(0xffffffffu, rv0 > 0);
    unsigned m1 = __ballot_sync(0xffffffffu, rv1 > 0);

    int  j0v = 0, j1v = 0, j2v = 0, j3v = 0;
    bool a0 = false, a1 = false, a2 = false, a3 = false;

    #define FIND_J(H, JV, AV)                                                      \
    {                                                                              \
        unsigned mh = ((m0 >> (8 * (H))) & 0xffu)                                  \
                    | ((m1 >> (8 * (H))) & 0xffu) << 8;                            \
        if (mh) { JV = __ffs(mh) - 1; AV = true; }                                 \
        else {   /* P = 2^-16 per head: essentially never */                       \
            const int base = ((H) << 24) | (i << NPOS);                            \
            for (int js = 16; js < S_LEN; js += 32) {                              \
                int vv = route_table[base + js + lane];                            \
                unsigned mm = __ballot_sync(0xffffffffu, vv > 0);                  \
                if (mm) { JV = js + __ffs(mm) - 1; AV = true; break; }             \
            }                                                                      \
        }                                                                          \
    }
    FIND_J(0, j0v, a0)
    FIND_J(1, j1v, a1)
    FIND_J(2, j2v, a2)
    FIND_J(3, j3v, a3)
    #undef FIND_J

    // ---- 2) token mask per head: shfl from prefetched rows (j<16 w.p. 1-2^-16) ----
    #define TOKMASK(JV, TM)                                                        \
    {                                                                              \
        if ((JV) < 16) {                                                           \
            unsigned sel = ((JV) < 8) ? ra : rb;                                   \
            TM = __shfl_sync(0xffffffffu, sel, ((JV) & 7) << 2) & 0xffffu;         \
        } else {                                                                   \
            int tv = (lane < TB) ? tokens[(JV) * TB + lane] : 0;                   \
            TM = __ballot_sync(0xffffffffu, tv > 0) & 0xffffu;                     \
        }                                                                          \
    }
    unsigned t0, t1, t2, t3;
    TOKMASK(j0v, t0)
    TOKMASK(j1v, t1)
    TOKMASK(j2v, t2)
    TOKMASK(j3v, t3)
    #undef TOKMASK

    // vin mask per head: bits 0..15 tokens, bits 16..27 pos bits (MSB-first pack)
    unsigned v0 = t0 | ((__brev((unsigned)j0v) >> 4) & 0x0fff0000u);
    unsigned v1 = t1 | ((__brev((unsigned)j1v) >> 4) & 0x0fff0000u);
    unsigned v2 = t2 | ((__brev((unsigned)j2v) >> 4) & 0x0fff0000u);
    unsigned v3 = t3 | ((__brev((unsigned)j3v) >> 4) & 0x0fff0000u);

    // lane role: lane<16 -> heads {0,2}, lane>=16 -> {1,3}
    const bool hiA = (lane & 16) != 0;
    const int  b   = lane & 15;
    const int  hA  = hiA ? 1 : 0;
    const int  hB  = hA + 2;

    const unsigned vA = hiA ? v1 : v0;
    const unsigned vB = hiA ? v3 : v2;
    const bool     aA = hiA ? a1 : a0;
    const bool     aB = hiA ? a3 : a2;

    // ---- 3) value lookups: this lane covers (hA,b) and (hB,b) ----
    int vaA = 0, vaB = 0;
    const int* cvA = &s_cv[(hA * TB + b) * VBITS];
    const int* cvB = &s_cv[(hB * TB + b) * VBITS];
    #pragma unroll
    for (int k = 0; k < VBITS; k++) {
        vaA = (vaA << 1) | (int)((vA >> cvA[k]) & 1u);
        vaB = (vaB << 1) | (int)((vB >> cvB[k]) & 1u);
    }
    float valA = __ldg(&value_table[(hA * TB + b) * (1 << VBITS) + vaA]);
    float valB = __ldg(&value_table[(hB * TB + b) * (1 << VBITS) + vaB]);
    bool c1 = aA && (valA > 0.5f);
    bool c2 = aB && (valB > 0.5f);

    unsigned clo = __ballot_sync(0xffffffffu, c1);  // head0 bits 0-15, head1 16-31
    unsigned chi = __ballot_sync(0xffffffffu, c2);  // head2 bits 0-15, head3 16-31
    unsigned long long comb = (unsigned long long)clo
                            | ((unsigned long long)chi << 32);

    // ---- 4) output lookup: lanes 0-15 ----
    if (lane < TB) {
        const int* co = &s_co[lane * OBITS];
        int oa = 0;
        #pragma unroll
        for (int k = 0; k < OBITS; k++) oa = (oa << 1) | (int)((comb >> co[k]) & 1ull);
        out[i * TB + lane] = __ldg(&output_table[lane * (1 << OBITS) + oa]);
    }
}

extern "C" void kernel_launch(void* const* d_in, const int* in_sizes, int n_in,
                              void* d_out, int out_size)
{
    const int*   tokens       = (const int*)  d_in[0];
    const int*   route_table  = (const int*)  d_in[1];
    const float* value_table  = (const float*)d_in[2];
    const float* output_table = (const float*)d_in[3];
    const int*   conns_value  = (const int*)  d_in[4];
    const int*   conns_out    = (const int*)  d_in[5];
    float*       out          = (float*)      d_out;

    poa_kernel<<<S_LEN / WARPS_PER_BLK, WARPS_PER_BLK * 32>>>(
        tokens, route_table, value_table, output_table,
        conns_value, conns_out, out);
}